// round 9
// baseline (speedup 1.0000x reference)
#include <cuda_runtime.h>
#include <math.h>
#include <stdint.h>

#define BATCH 8
#define NPTS 2048
#define GRIDX 64             // blocks per batch along rows
#define ROWS_PER_BLOCK 32    // 8 warps * 4 rows

// First CACHE_BYTES of M are loaded with .cg (L2-allocate, stays resident
// across graph replays); the rest with .cs (evict-first) so the streaming
// tail absorbs L2 evictions instead of thrashing the resident set.
#define CACHE_BYTES (116ull << 20)

__device__ float g_part[BATCH][GRIDX][12];
__device__ unsigned int g_count[BATCH];   // zero-init; reset each call

template <int LDMODE>   // 0 = .cg (resident), 1 = .cs (streaming)
__device__ __forceinline__ float4 ldM(const float4* p) {
    return (LDMODE == 0) ? __ldcg(p) : __ldcs(p);
}

// Stream 4 rows x NPTS cols of M; accumulate 12 partial dots in d[].
// d[3r + c] = partial dot of row r with P component c.
template <int LDMODE>
__device__ __forceinline__ void streamRows(
    const float4* __restrict__ Rbase,
    const float* __restrict__ p0,
    const float* __restrict__ p1,
    const float* __restrict__ p2,
    int lane, float d[12]) {
    #pragma unroll 4
    for (int it = 0; it < NPTS / 128; it++) {     // 16 iterations
        int m4 = it * 32 + lane;
        float4 mv0 = ldM<LDMODE>(&Rbase[m4]);
        float4 mv1 = ldM<LDMODE>(&Rbase[m4 + 1 * (NPTS / 4)]);
        float4 mv2 = ldM<LDMODE>(&Rbase[m4 + 2 * (NPTS / 4)]);
        float4 mv3 = ldM<LDMODE>(&Rbase[m4 + 3 * (NPTS / 4)]);
        int m = m4 * 4;
        float4 a  = *reinterpret_cast<const float4*>(&p0[m]);
        float4 bb = *reinterpret_cast<const float4*>(&p1[m]);
        float4 c  = *reinterpret_cast<const float4*>(&p2[m]);
        d[0]  += mv0.x * a.x  + mv0.y * a.y  + mv0.z * a.z  + mv0.w * a.w;
        d[1]  += mv0.x * bb.x + mv0.y * bb.y + mv0.z * bb.z + mv0.w * bb.w;
        d[2]  += mv0.x * c.x  + mv0.y * c.y  + mv0.z * c.z  + mv0.w * c.w;
        d[3]  += mv1.x * a.x  + mv1.y * a.y  + mv1.z * a.z  + mv1.w * a.w;
        d[4]  += mv1.x * bb.x + mv1.y * bb.y + mv1.z * bb.z + mv1.w * bb.w;
        d[5]  += mv1.x * c.x  + mv1.y * c.y  + mv1.z * c.z  + mv1.w * c.w;
        d[6]  += mv2.x * a.x  + mv2.y * a.y  + mv2.z * a.z  + mv2.w * a.w;
        d[7]  += mv2.x * bb.x + mv2.y * bb.y + mv2.z * bb.z + mv2.w * bb.w;
        d[8]  += mv2.x * c.x  + mv2.y * c.y  + mv2.z * c.z  + mv2.w * c.w;
        d[9]  += mv3.x * a.x  + mv3.y * a.y  + mv3.z * a.z  + mv3.w * a.w;
        d[10] += mv3.x * bb.x + mv3.y * bb.y + mv3.z * bb.z + mv3.w * bb.w;
        d[11] += mv3.x * c.x  + mv3.y * c.y  + mv3.z * c.z  + mv3.w * c.w;
    }
}

// ---------------------------------------------------------------------------
// Fused kernel. grid = (GRIDX, BATCH), block = 256 (8 warps), 4 rows/warp.
// Last block per batch reduces partials -> means, S, polar, R, t.
// ---------------------------------------------------------------------------
__global__ void __launch_bounds__(256, 5) fused_kernel(
    const float* __restrict__ P,
    const float* __restrict__ Q,
    const float* __restrict__ M,
    float* __restrict__ out) {
    const int b = blockIdx.y;
    const int tid = threadIdx.x;
    const int warp = tid >> 5;
    const int lane = tid & 31;

    __shared__ float p0[NPTS], p1[NPTS], p2[NPTS];
    __shared__ float sacc[8][12];
    __shared__ float warpSums[8][6];
    __shared__ float sTv[12];
    __shared__ int sIsLast;

    const float* Pb = P + (size_t)b * NPTS * 3;
    const float* Qb = Q + (size_t)b * NPTS * 3;

    for (int i = tid; i < NPTS * 3; i += 256) {
        float v = Pb[i];
        int pt = i / 3, c = i - pt * 3;
        float* dst = (c == 0) ? p0 : (c == 1) ? p1 : p2;
        dst[pt] = v;
    }
    __syncthreads();

    // ---------------- Phase 1: stream 4 rows of M per warp ----------------
    const size_t blockOff = (size_t)b * NPTS * NPTS + (size_t)blockIdx.x * ROWS_PER_BLOCK * NPTS;
    const int n0 = blockIdx.x * ROWS_PER_BLOCK + warp * 4;
    const float4* Rbase =
        reinterpret_cast<const float4*>(M + blockOff + (size_t)(warp * 4) * NPTS);

    float d[12];
    #pragma unroll
    for (int i = 0; i < 12; i++) d[i] = 0.f;

    if (blockOff * 4 < CACHE_BYTES)
        streamRows<0>(Rbase, p0, p1, p2, lane, d);   // L2-resident region
    else
        streamRows<1>(Rbase, p0, p1, p2, lane, d);   // streaming tail

    #pragma unroll
    for (int off = 16; off > 0; off >>= 1) {
        #pragma unroll
        for (int j = 0; j < 12; j++)
            d[j] += __shfl_xor_sync(0xffffffffu, d[j], off);
    }

    if (lane == 0) {
        const float* q = Qb + n0 * 3;
        float q0x = q[0], q0y = q[1],  q0z = q[2];
        float q1x = q[3], q1y = q[4],  q1z = q[5];
        float q2x = q[6], q2y = q[7],  q2z = q[8];
        float q3x = q[9], q3y = q[10], q3z = q[11];
        sacc[warp][0] = d[0] * q0x + d[3] * q1x + d[6] * q2x + d[9]  * q3x;
        sacc[warp][1] = d[0] * q0y + d[3] * q1y + d[6] * q2y + d[9]  * q3y;
        sacc[warp][2] = d[0] * q0z + d[3] * q1z + d[6] * q2z + d[9]  * q3z;
        sacc[warp][3] = d[1] * q0x + d[4] * q1x + d[7] * q2x + d[10] * q3x;
        sacc[warp][4] = d[1] * q0y + d[4] * q1y + d[7] * q2y + d[10] * q3y;
        sacc[warp][5] = d[1] * q0z + d[4] * q1z + d[7] * q2z + d[10] * q3z;
        sacc[warp][6] = d[2] * q0x + d[5] * q1x + d[8] * q2x + d[11] * q3x;
        sacc[warp][7] = d[2] * q0y + d[5] * q1y + d[8] * q2y + d[11] * q3y;
        sacc[warp][8] = d[2] * q0z + d[5] * q1z + d[8] * q2z + d[11] * q3z;
        sacc[warp][9]  = d[0] + d[3] + d[6] + d[9];
        sacc[warp][10] = d[1] + d[4] + d[7] + d[10];
        sacc[warp][11] = d[2] + d[5] + d[8] + d[11];
    }
    __syncthreads();
    if (tid < 12) {
        float s = 0.f;
        #pragma unroll
        for (int w = 0; w < 8; w++) s += sacc[w][tid];
        g_part[b][blockIdx.x][tid] = s;
    }
    __threadfence();
    __syncthreads();

    // ---------------- Phase 2: last block of this batch finishes ----------------
    if (tid == 0) {
        unsigned int old = atomicAdd(&g_count[b], 1u);
        sIsLast = (old == GRIDX - 1u) ? 1 : 0;
    }
    __syncthreads();
    if (!sIsLast) return;
    __threadfence();   // acquire: make other blocks' g_part writes visible

    // --- means: P from smem, Q via float4 triples from global ---
    float sp0 = 0.f, sp1 = 0.f, sp2 = 0.f;
    for (int n = tid; n < NPTS; n += 256) {
        sp0 += p0[n]; sp1 += p1[n]; sp2 += p2[n];
    }
    float sq0 = 0.f, sq1 = 0.f, sq2 = 0.f;
    const float4* Q4 = reinterpret_cast<const float4*>(Qb);
    #pragma unroll
    for (int t = 0; t < 2; t++) {
        int tr = tid + t * 256;               // triple index, 512 total
        float4 A = Q4[tr * 3 + 0];
        float4 Bv = Q4[tr * 3 + 1];
        float4 C = Q4[tr * 3 + 2];
        sq0 += A.x + A.w + Bv.z + C.y;
        sq1 += A.y + Bv.x + Bv.w + C.z;
        sq2 += A.z + Bv.y + C.x + C.w;
    }
    #pragma unroll
    for (int off = 16; off > 0; off >>= 1) {
        sp0 += __shfl_xor_sync(0xffffffffu, sp0, off);
        sp1 += __shfl_xor_sync(0xffffffffu, sp1, off);
        sp2 += __shfl_xor_sync(0xffffffffu, sp2, off);
        sq0 += __shfl_xor_sync(0xffffffffu, sq0, off);
        sq1 += __shfl_xor_sync(0xffffffffu, sq1, off);
        sq2 += __shfl_xor_sync(0xffffffffu, sq2, off);
    }
    if (lane == 0) {
        warpSums[warp][0] = sp0; warpSums[warp][1] = sp1; warpSums[warp][2] = sp2;
        warpSums[warp][3] = sq0; warpSums[warp][4] = sq1; warpSums[warp][5] = sq2;
    }

    // --- warp 0 reduces the GRIDX x 12 partials ---
    if (warp == 0) {
        float Tv[12];
        #pragma unroll
        for (int j = 0; j < 12; j++) Tv[j] = 0.f;
        #pragma unroll
        for (int r = 0; r < GRIDX / 32; r++) {
            const float* row = g_part[b][lane + r * 32];
            #pragma unroll
            for (int j = 0; j < 12; j++) Tv[j] += row[j];
        }
        #pragma unroll
        for (int off = 16; off > 0; off >>= 1) {
            #pragma unroll
            for (int j = 0; j < 12; j++)
                Tv[j] += __shfl_xor_sync(0xffffffffu, Tv[j], off);
        }
        if (lane == 0) {
            #pragma unroll
            for (int j = 0; j < 12; j++) sTv[j] = Tv[j];
        }
    }
    __syncthreads();

    if (tid == 0) {
        g_count[b] = 0u;   // reset for next graph replay

        float mS[6];
        #pragma unroll
        for (int j = 0; j < 6; j++) {
            float s = 0.f;
            #pragma unroll
            for (int w = 0; w < 8; w++) s += warpSums[w][j];
            mS[j] = s;
        }
        const float inv = 1.0f / (float)NPTS;
        float mp0 = mS[0] * inv, mp1 = mS[1] * inv, mp2 = mS[2] * inv;
        float mq0 = mS[3] * inv, mq1 = mS[4] * inv, mq2 = mS[5] * inv;

        float v0 = sTv[9], v1 = sTv[10], v2 = sTv[11];
        float X[9];
        X[0] = sTv[0] - v0 * mq0; X[1] = sTv[1] - v0 * mq1; X[2] = sTv[2] - v0 * mq2;
        X[3] = sTv[3] - v1 * mq0; X[4] = sTv[4] - v1 * mq1; X[5] = sTv[5] - v1 * mq2;
        X[6] = sTv[6] - v2 * mq0; X[7] = sTv[7] - v2 * mq1; X[8] = sTv[8] - v2 * mq2;

        // Newton polar iteration (det-scaled): X -> 0.5*(g*X + sgn*g^2*cof(X))
        #pragma unroll
        for (int it = 0; it < 12; it++) {
            float C[9];
            C[0] = X[4] * X[8] - X[5] * X[7];
            C[1] = X[5] * X[6] - X[3] * X[8];
            C[2] = X[3] * X[7] - X[4] * X[6];
            C[3] = X[2] * X[7] - X[1] * X[8];
            C[4] = X[0] * X[8] - X[2] * X[6];
            C[5] = X[1] * X[6] - X[0] * X[7];
            C[6] = X[1] * X[5] - X[2] * X[4];
            C[7] = X[2] * X[3] - X[0] * X[5];
            C[8] = X[0] * X[4] - X[1] * X[3];
            float det = X[0] * C[0] + X[1] * C[1] + X[2] * C[2];
            float g = rcbrtf(fabsf(det));
            float g2s = copysignf(g * g, det);
            #pragma unroll
            for (int i = 0; i < 9; i++) X[i] = 0.5f * (g * X[i] + g2s * C[i]);
        }

        float R[9];
        #pragma unroll
        for (int i = 0; i < 3; i++)
            #pragma unroll
            for (int j = 0; j < 3; j++)
                R[i * 3 + j] = X[j * 3 + i];

        float* Rout = out + b * 9;
        float* tout = out + BATCH * 9 + b * 3;
        float mp[3] = {mp0, mp1, mp2};
        float mq[3] = {mq0, mq1, mq2};
        #pragma unroll
        for (int i = 0; i < 3; i++) {
            float ti = mq[i];
            #pragma unroll
            for (int j = 0; j < 3; j++) {
                Rout[i * 3 + j] = R[i * 3 + j];
                ti -= R[i * 3 + j] * mp[j];
            }
            tout[i] = ti;
        }
    }
}

// ---------------------------------------------------------------------------
extern "C" void kernel_launch(void* const* d_in, const int* in_sizes, int n_in,
                              void* d_out, int out_size) {
    const float* P = (const float*)d_in[0];   // Ppc [8,2048,3]
    const float* Q = (const float*)d_in[1];   // Qpc [8,2048,3]
    const float* M = (const float*)d_in[2];   // M   [8,2048,2048]
    float* out = (float*)d_out;               // 72 R + 24 t

    fused_kernel<<<dim3(GRIDX, BATCH), 256>>>(P, Q, M, out);
}